// round 2
// baseline (speedup 1.0000x reference)
#include <cuda_runtime.h>
#include <cstdint>

// Geometry
#define DIN    1024
#define DOUT   1024
#define MTOT   32768            // B*S
#define K2     512              // compacted K (2:4 column-global mask)
#define BM     128
#define BN     256
#define BK     32
#define KCH    (K2 / BK)        // 16 k-chunks
#define MT     (MTOT / BM)      // 256
#define NT     (DOUT / BN)      // 4
#define THREADS 256
#define STAGES 4

// Fragment-major compact operands (written by prepass, read by GEMM).
// A frag tile = 16 rows x 8 k = 512B; layout [mt][kc][mtl(8)][ks(4)][lane(32)][4B*4]
// B frag tile = 16 n x 8 k   = 512B; layout [nt][kc][p(16)][ks(4)][lane(32)][4B*4]
#define A_STAGE_BYTES (BM * BK * 4)    // 16384
#define B_STAGE_BYTES (BN * BK * 4)    // 32768
__device__ __align__(128) unsigned char g_xc[(size_t)MT * KCH * A_STAGE_BYTES]; // 64 MB
__device__ __align__(128) unsigned char g_wc[(size_t)NT * KCH * B_STAGE_BYTES]; //  2 MB
__device__ int g_kidx[K2];

// ------------------------------------------------------------------ helpers
__device__ __forceinline__ uint32_t smem_u32(const void* p) {
    uint32_t a;
    asm("{ .reg .u64 t; cvta.to.shared.u64 t, %1; cvt.u32.u64 %0, t; }"
        : "=r"(a) : "l"(p));
    return a;
}
__device__ __forceinline__ uint32_t f2tf32(float f) {
    uint32_t r;
    asm("cvt.rna.tf32.f32 %0, %1;" : "=r"(r) : "f"(f));
    return r;
}
__device__ __forceinline__ void cp16(uint32_t dst, const void* src) {
    asm volatile("cp.async.cg.shared.global [%0], [%1], 16;"
                 :: "r"(dst), "l"(src) : "memory");
}
__device__ __forceinline__ void cp_commit() {
    asm volatile("cp.async.commit_group;" ::: "memory");
}
template <int N>
__device__ __forceinline__ void cp_wait() {
    asm volatile("cp.async.wait_group %0;" :: "n"(N) : "memory");
}
__device__ __forceinline__ void lds128(uint32_t (&r)[4], uint32_t addr) {
    asm volatile("ld.shared.v4.u32 {%0,%1,%2,%3}, [%4];"
                 : "=r"(r[0]), "=r"(r[1]), "=r"(r[2]), "=r"(r[3]) : "r"(addr));
}
__device__ __forceinline__ void mma_tf32(float (&d)[4], const uint32_t (&a)[4],
                                         uint32_t b0, uint32_t b1) {
    asm volatile(
        "mma.sync.aligned.m16n8k8.row.col.f32.tf32.tf32.f32 "
        "{%0,%1,%2,%3}, {%4,%5,%6,%7}, {%8,%9}, {%0,%1,%2,%3};"
        : "+f"(d[0]), "+f"(d[1]), "+f"(d[2]), "+f"(d[3])
        : "r"(a[0]), "r"(a[1]), "r"(a[2]), "r"(a[3]), "r"(b0), "r"(b1));
}

// ------------------------------------------------------------------ prepass
// Mask is column-global (2 active per 4-group, all rows identical). One thread
// per 4-group writes its (up to 2) active column indices in order.
__global__ void build_kidx_kernel(const float* __restrict__ mask) {
    int g = blockIdx.x * blockDim.x + threadIdx.x;   // 256 groups
    if (g >= DIN / 4) return;
    int w = 0;
    int idx[2] = {-1, -1};
    #pragma unroll
    for (int j = 0; j < 4; j++) {
        int c = g * 4 + j;
        if (mask[c] != 0.0f && w < 2) idx[w++] = c;
    }
    g_kidx[2 * g]     = idx[0];
    g_kidx[2 * g + 1] = idx[1];
}

// A fragment-major compaction: frag fi = ((mt*KCH + kc)*8 + mtl)*4 + ks.
// One warp per 512B fragment. 131072 frags -> 16384 blocks x 256.
__global__ void __launch_bounds__(256) compact_x_kernel(const float* __restrict__ x) {
    int fi = blockIdx.x * 8 + (threadIdx.x >> 5);
    int l  = threadIdx.x & 31;
    int ks  = fi & 3;
    int mtl = (fi >> 2) & 7;
    int kc  = (fi >> 5) & (KCH - 1);
    int mt  = fi >> 9;
    int r   = mt * BM + mtl * 16 + (l >> 2);          // rows r, r+8
    int kk  = kc * BK + ks * 8 + (l & 3);             // compact cols kk, kk+4
    int k0 = g_kidx[kk], k1 = g_kidx[kk + 4];
    const float* xr0 = x + (size_t)r * DIN;
    const float* xr1 = xr0 + (size_t)8 * DIN;
    uint32_t v0 = (k0 >= 0) ? f2tf32(__ldg(xr0 + k0)) : 0u;
    uint32_t v1 = (k0 >= 0) ? f2tf32(__ldg(xr1 + k0)) : 0u;
    uint32_t v2 = (k1 >= 0) ? f2tf32(__ldg(xr0 + k1)) : 0u;
    uint32_t v3 = (k1 >= 0) ? f2tf32(__ldg(xr1 + k1)) : 0u;
    uint4* dst = reinterpret_cast<uint4*>(g_xc + (size_t)fi * 512 + l * 16);
    *dst = make_uint4(v0, v1, v2, v3);
}

// B fragment-major: frag fj = ((nt*KCH + kc)*16 + p)*4 + ks; npair p covers
// ntiles 2p,2p+1 (16 n-cols). lane regs: {b0_t0, b1_t0, b0_t1, b1_t1}.
__global__ void __launch_bounds__(256) compact_w_kernel(const float* __restrict__ w) {
    int fj = blockIdx.x * 8 + (threadIdx.x >> 5);
    int l  = threadIdx.x & 31;
    int ks = fj & 3;
    int p  = (fj >> 2) & 15;
    int kc = (fj >> 6) & (KCH - 1);
    int nt = fj >> 10;
    int n0 = nt * BN + p * 16 + (l >> 2);             // ntile0 col; ntile1 = n0+8
    int kk = kc * BK + ks * 8 + (l & 3);
    int k0 = g_kidx[kk], k1 = g_kidx[kk + 4];
    const float* w0 = w + (size_t)n0 * DIN;
    const float* w1 = w0 + (size_t)8 * DIN;
    uint32_t v0 = (k0 >= 0) ? f2tf32(__ldg(w0 + k0)) : 0u;
    uint32_t v1 = (k1 >= 0) ? f2tf32(__ldg(w0 + k1)) : 0u;
    uint32_t v2 = (k0 >= 0) ? f2tf32(__ldg(w1 + k0)) : 0u;
    uint32_t v3 = (k1 >= 0) ? f2tf32(__ldg(w1 + k1)) : 0u;
    uint4* dst = reinterpret_cast<uint4*>(g_wc + (size_t)fj * 512 + l * 16);
    *dst = make_uint4(v0, v1, v2, v3);
}

// ------------------------------------------------------------------ GEMM
// smem: A stages [0, 4*16KB) then B stages [64KB, 64KB+4*32KB) = 192KB total.
#define SMEM_BYTES (STAGES * (A_STAGE_BYTES + B_STAGE_BYTES))   // 196608

__global__ void __launch_bounds__(THREADS, 1) gemm_kernel(float* __restrict__ out) {
    extern __shared__ char smem[];
    const uint32_t sA0 = smem_u32(smem);
    const uint32_t sB0 = sA0 + STAGES * A_STAGE_BYTES;

    const int tid = threadIdx.x;
    const int wid = tid >> 5, lid = tid & 31;
    const int nt = blockIdx.x, mt = blockIdx.y;
    const int wm = wid & 1;         // 2 m-warps (64 rows each)
    const int wn = wid >> 1;        // 4 n-warps (64 cols each)

    const unsigned char* gA = g_xc + ((size_t)mt * KCH) * A_STAGE_BYTES;
    const unsigned char* gB = g_wc + ((size_t)nt * KCH) * B_STAGE_BYTES;

    // stage loader: A 16KB (4 chunks/thread), B 32KB (8 chunks/thread)
    auto load_stage = [&](int s, int c) {
        uint32_t dA = sA0 + s * A_STAGE_BYTES + tid * 16;
        const unsigned char* srcA = gA + (size_t)c * A_STAGE_BYTES + tid * 16;
        #pragma unroll
        for (int j = 0; j < 4; j++) cp16(dA + j * 4096, srcA + j * 4096);
        uint32_t dB = sB0 + s * B_STAGE_BYTES + tid * 16;
        const unsigned char* srcB = gB + (size_t)c * B_STAGE_BYTES + tid * 16;
        #pragma unroll
        for (int j = 0; j < 8; j++) cp16(dB + j * 4096, srcB + j * 4096);
    };

    float acc[4][8][4];
    #pragma unroll
    for (int i = 0; i < 4; i++)
        #pragma unroll
        for (int j = 0; j < 8; j++)
            #pragma unroll
            for (int v = 0; v < 4; v++) acc[i][j][v] = 0.0f;

    // prologue: fill 3 stages
    #pragma unroll
    for (int s = 0; s < STAGES - 1; s++) { load_stage(s, s); cp_commit(); }
    cp_wait<STAGES - 2>();
    __syncthreads();

    const uint32_t aBase = sA0 + lid * 16;
    const uint32_t bBase = sB0 + lid * 16;

    for (int c = 0; c < KCH; c++) {
        const int s = c & (STAGES - 1);
        const uint32_t aStage = aBase + s * A_STAGE_BYTES + (wm * 4) * 4 * 512;
        const uint32_t bStage = bBase + s * B_STAGE_BYTES + (wn * 4) * 4 * 512;
        #pragma unroll
        for (int ks = 0; ks < 4; ks++) {
            uint32_t a[4][4];
            #pragma unroll
            for (int i = 0; i < 4; i++)
                lds128(a[i], aStage + (i * 4 + ks) * 512);
            uint32_t b[4][4];
            #pragma unroll
            for (int jp = 0; jp < 4; jp++)
                lds128(b[jp], bStage + (jp * 4 + ks) * 512);
            #pragma unroll
            for (int i = 0; i < 4; i++)
                #pragma unroll
                for (int jp = 0; jp < 4; jp++) {
                    mma_tf32(acc[i][2 * jp],     a[i], b[jp][0], b[jp][1]);
                    mma_tf32(acc[i][2 * jp + 1], a[i], b[jp][2], b[jp][3]);
                }
        }
        if (c + STAGES - 1 < KCH) load_stage((c + STAGES - 1) & (STAGES - 1),
                                             c + STAGES - 1);
        cp_commit();
        cp_wait<STAGES - 2>();
        __syncthreads();
    }

    // epilogue: D frag (r=grp, c=2*tig): c0,c1 @ row r; c2,c3 @ row r+8
    const int rowW = mt * BM + wm * 64 + (lid >> 2);
    const int colW = nt * BN + wn * 64 + (lid & 3) * 2;
    #pragma unroll
    for (int i = 0; i < 4; i++) {
        const size_t r0 = (size_t)(rowW + i * 16) * DOUT;
        const size_t r1 = r0 + (size_t)8 * DOUT;
        #pragma unroll
        for (int t = 0; t < 8; t++) {
            const int cc = colW + t * 8;
            *reinterpret_cast<float2*>(out + r0 + cc) =
                make_float2(acc[i][t][0], acc[i][t][1]);
            *reinterpret_cast<float2*>(out + r1 + cc) =
                make_float2(acc[i][t][2], acc[i][t][3]);
        }
    }
}

// ------------------------------------------------------------------ launch
extern "C" void kernel_launch(void* const* d_in, const int* in_sizes, int n_in,
                              void* d_out, int out_size) {
    const float* x    = (const float*)d_in[0];
    const float* w    = (const float*)d_in[1];
    const float* mask = (const float*)d_in[2];
    float* out        = (float*)d_out;

    static bool attr_done = false;
    if (!attr_done) {
        cudaFuncSetAttribute(gemm_kernel,
                             cudaFuncAttributeMaxDynamicSharedMemorySize, SMEM_BYTES);
        attr_done = true;
    }

    build_kidx_kernel<<<1, 256>>>(mask);
    compact_x_kernel<<<(MT * KCH * 8 * 4) / 8, 256>>>(x);   // 16384 blocks
    compact_w_kernel<<<(NT * KCH * 16 * 4) / 8, 256>>>(w);  //   512 blocks
    gemm_kernel<<<dim3(NT, MT), THREADS, SMEM_BYTES>>>(out);
}

// round 3
// speedup vs baseline: 1.0520x; 1.0520x over previous
#include <cuda_runtime.h>
#include <cstdint>

// Geometry
#define DIN    1024
#define DOUT   1024
#define MTOT   32768            // B*S
#define K2     512              // compacted K (2:4 column-global mask)
#define BM     128
#define BN     128
#define BK     32
#define KCH    (K2 / BK)        // 16 k-chunks
#define MT     (MTOT / BM)      // 256
#define NT     (DOUT / BN)      // 8
#define THREADS 256
#define STAGES 3

// Fragment-major compact operands (written by prepass, read by GEMM).
// A frag tile = 16 rows x 8 k = 512B; layout [mt][kc][mtl(8)][ks(4)][lane(32)][16B]
// B frag pair = 16 n   x 8 k = 512B; layout [nt][kc][p(8)][ks(4)][lane(32)][16B]
#define A_STAGE_BYTES (BM * BK * 4)    // 16384
#define B_STAGE_BYTES (BN * BK * 4)    // 16384
__device__ __align__(128) unsigned char g_xc[(size_t)MT * KCH * A_STAGE_BYTES]; // 64 MB
__device__ __align__(128) unsigned char g_wc[(size_t)NT * KCH * B_STAGE_BYTES]; //  2 MB
__device__ int g_kidx[K2];

// ------------------------------------------------------------------ helpers
__device__ __forceinline__ uint32_t smem_u32(const void* p) {
    uint32_t a;
    asm("{ .reg .u64 t; cvta.to.shared.u64 t, %1; cvt.u32.u64 %0, t; }"
        : "=r"(a) : "l"(p));
    return a;
}
__device__ __forceinline__ uint32_t f2tf32(float f) {
    uint32_t r;
    asm("cvt.rna.tf32.f32 %0, %1;" : "=r"(r) : "f"(f));
    return r;
}
__device__ __forceinline__ void cp16(uint32_t dst, const void* src) {
    asm volatile("cp.async.cg.shared.global [%0], [%1], 16;"
                 :: "r"(dst), "l"(src) : "memory");
}
__device__ __forceinline__ void cp_commit() {
    asm volatile("cp.async.commit_group;" ::: "memory");
}
template <int N>
__device__ __forceinline__ void cp_wait() {
    asm volatile("cp.async.wait_group %0;" :: "n"(N) : "memory");
}
__device__ __forceinline__ void lds128(uint32_t (&r)[4], uint32_t addr) {
    asm volatile("ld.shared.v4.u32 {%0,%1,%2,%3}, [%4];"
                 : "=r"(r[0]), "=r"(r[1]), "=r"(r[2]), "=r"(r[3]) : "r"(addr));
}
__device__ __forceinline__ void mma_tf32(float (&d)[4], const uint32_t (&a)[4],
                                         uint32_t b0, uint32_t b1) {
    asm volatile(
        "mma.sync.aligned.m16n8k8.row.col.f32.tf32.tf32.f32 "
        "{%0,%1,%2,%3}, {%4,%5,%6,%7}, {%8,%9}, {%0,%1,%2,%3};"
        : "+f"(d[0]), "+f"(d[1]), "+f"(d[2]), "+f"(d[3])
        : "r"(a[0]), "r"(a[1]), "r"(a[2]), "r"(a[3]), "r"(b0), "r"(b1));
}

// ------------------------------------------------------------------ prepass
// Mask is column-global: one thread per 4-group records its 2 active columns.
__global__ void build_kidx_kernel(const float* __restrict__ mask) {
    int g = blockIdx.x * blockDim.x + threadIdx.x;   // 256 groups
    if (g >= DIN / 4) return;
    int w = 0;
    int idx[2] = {-1, -1};
    #pragma unroll
    for (int j = 0; j < 4; j++) {
        int c = g * 4 + j;
        if (mask[c] != 0.0f && w < 2) idx[w++] = c;
    }
    g_kidx[2 * g]     = idx[0];
    g_kidx[2 * g + 1] = idx[1];
}

// A fragment-major compaction: frag fi = ((mt*KCH + kc)*8 + mtl)*4 + ks.
// One warp per 512B fragment. 131072 frags -> 16384 blocks x 256.
__global__ void __launch_bounds__(256) compact_x_kernel(const float* __restrict__ x) {
    int fi = blockIdx.x * 8 + (threadIdx.x >> 5);
    int l  = threadIdx.x & 31;
    int ks  = fi & 3;
    int mtl = (fi >> 2) & 7;
    int kc  = (fi >> 5) & (KCH - 1);
    int mt  = fi >> 9;
    int r   = mt * BM + mtl * 16 + (l >> 2);          // rows r, r+8
    int kk  = kc * BK + ks * 8 + (l & 3);             // compact cols kk, kk+4
    int k0 = g_kidx[kk], k1 = g_kidx[kk + 4];
    const float* xr0 = x + (size_t)r * DIN;
    const float* xr1 = xr0 + (size_t)8 * DIN;
    uint32_t v0 = (k0 >= 0) ? f2tf32(__ldg(xr0 + k0)) : 0u;
    uint32_t v1 = (k0 >= 0) ? f2tf32(__ldg(xr1 + k0)) : 0u;
    uint32_t v2 = (k1 >= 0) ? f2tf32(__ldg(xr0 + k1)) : 0u;
    uint32_t v3 = (k1 >= 0) ? f2tf32(__ldg(xr1 + k1)) : 0u;
    uint4* dst = reinterpret_cast<uint4*>(g_xc + (size_t)fi * 512 + l * 16);
    *dst = make_uint4(v0, v1, v2, v3);
}

// B fragment-major: frag fj = ((nt*KCH + kc)*8 + p)*4 + ks; pair p covers
// ntiles 2p,2p+1 (16 n-cols). lane regs: {b0_t0, b1_t0, b0_t1, b1_t1}.
// Total frags = 8*16*8*4 = 4096 -> 512 blocks x 256.
__global__ void __launch_bounds__(256) compact_w_kernel(const float* __restrict__ w) {
    int fj = blockIdx.x * 8 + (threadIdx.x >> 5);
    int l  = threadIdx.x & 31;
    int ks = fj & 3;
    int p  = (fj >> 2) & 7;
    int kc = (fj >> 5) & (KCH - 1);
    int nt = fj >> 9;
    int n0 = nt * BN + p * 16 + (l >> 2);             // ntile0 col; ntile1 = n0+8
    int kk = kc * BK + ks * 8 + (l & 3);
    int k0 = g_kidx[kk], k1 = g_kidx[kk + 4];
    const float* w0 = w + (size_t)n0 * DIN;
    const float* w1 = w0 + (size_t)8 * DIN;
    uint32_t v0 = (k0 >= 0) ? f2tf32(__ldg(w0 + k0)) : 0u;
    uint32_t v1 = (k1 >= 0) ? f2tf32(__ldg(w0 + k1)) : 0u;
    uint32_t v2 = (k0 >= 0) ? f2tf32(__ldg(w1 + k0)) : 0u;
    uint32_t v3 = (k1 >= 0) ? f2tf32(__ldg(w1 + k1)) : 0u;
    uint4* dst = reinterpret_cast<uint4*>(g_wc + (size_t)fj * 512 + l * 16);
    *dst = make_uint4(v0, v1, v2, v3);
}

// ------------------------------------------------------------------ GEMM
// smem: A stages [0, 3*16KB) then B stages [48KB, 48KB+3*16KB) = 96KB.
#define SMEM_BYTES (STAGES * (A_STAGE_BYTES + B_STAGE_BYTES))   // 98304

__global__ void __launch_bounds__(THREADS, 2) gemm_kernel(float* __restrict__ out) {
    extern __shared__ char smem[];
    const uint32_t sA0 = smem_u32(smem);
    const uint32_t sB0 = sA0 + STAGES * A_STAGE_BYTES;

    const int tid = threadIdx.x;
    const int wid = tid >> 5, lid = tid & 31;
    const int nt = blockIdx.x, mt = blockIdx.y;
    const int wm = wid & 1;         // 2 m-warps (64 rows each)
    const int wn = wid >> 1;        // 4 n-warps (32 cols each = 2 pairs)

    const unsigned char* gA = g_xc + ((size_t)mt * KCH) * A_STAGE_BYTES;
    const unsigned char* gB = g_wc + ((size_t)nt * KCH) * B_STAGE_BYTES;

    // stage loader: A 16KB + B 16KB, 256 threads x 16B -> 4 iters each
    auto load_stage = [&](int s, int c) {
        uint32_t dA = sA0 + s * A_STAGE_BYTES + tid * 16;
        const unsigned char* srcA = gA + (size_t)c * A_STAGE_BYTES + tid * 16;
        #pragma unroll
        for (int j = 0; j < 4; j++) cp16(dA + j * 4096, srcA + j * 4096);
        uint32_t dB = sB0 + s * B_STAGE_BYTES + tid * 16;
        const unsigned char* srcB = gB + (size_t)c * B_STAGE_BYTES + tid * 16;
        #pragma unroll
        for (int j = 0; j < 4; j++) cp16(dB + j * 4096, srcB + j * 4096);
    };

    float acc[4][4][4];
    #pragma unroll
    for (int i = 0; i < 4; i++)
        #pragma unroll
        for (int j = 0; j < 4; j++)
            #pragma unroll
            for (int v = 0; v < 4; v++) acc[i][j][v] = 0.0f;

    // prologue: fill stages 0,1
    load_stage(0, 0); cp_commit();
    load_stage(1, 1); cp_commit();
    cp_wait<1>();
    __syncthreads();

    const uint32_t aBase = sA0 + lid * 16;
    const uint32_t bBase = sB0 + lid * 16;

    int s = 0, sload = 2;
    for (int c = 0; c < KCH; c++) {
        // issue load for chunk c+2 FIRST so it overlaps this chunk's MMAs
        if (c + 2 < KCH) load_stage(sload, c + 2);
        cp_commit();

        const uint32_t aStage = aBase + s * A_STAGE_BYTES + (wm * 4) * 4 * 512;
        const uint32_t bStage = bBase + s * B_STAGE_BYTES + (wn * 2) * 4 * 512;
        #pragma unroll
        for (int ks = 0; ks < 4; ks++) {
            uint32_t a[4][4];
            #pragma unroll
            for (int i = 0; i < 4; i++)
                lds128(a[i], aStage + (i * 4 + ks) * 512);
            uint32_t b[2][4];
            #pragma unroll
            for (int jp = 0; jp < 2; jp++)
                lds128(b[jp], bStage + (jp * 4 + ks) * 512);
            #pragma unroll
            for (int i = 0; i < 4; i++)
                #pragma unroll
                for (int jp = 0; jp < 2; jp++) {
                    mma_tf32(acc[i][2 * jp],     a[i], b[jp][0], b[jp][1]);
                    mma_tf32(acc[i][2 * jp + 1], a[i], b[jp][2], b[jp][3]);
                }
        }

        cp_wait<1>();           // chunk c+1's data now resident
        __syncthreads();
        s     = (s == STAGES - 1) ? 0 : s + 1;
        sload = (sload == STAGES - 1) ? 0 : sload + 1;
    }

    // epilogue: ntile j at warp col base + 8*j; frag cols (l&3)*2, rows r, r+8
    const int rowW = mt * BM + wm * 64 + (lid >> 2);
    const int colW = nt * BN + wn * 32 + (lid & 3) * 2;
    #pragma unroll
    for (int i = 0; i < 4; i++) {
        const size_t r0 = (size_t)(rowW + i * 16) * DOUT;
        const size_t r1 = r0 + (size_t)8 * DOUT;
        #pragma unroll
        for (int j = 0; j < 4; j++) {
            const int cc = colW + j * 8;
            *reinterpret_cast<float2*>(out + r0 + cc) =
                make_float2(acc[i][j][0], acc[i][j][1]);
            *reinterpret_cast<float2*>(out + r1 + cc) =
                make_float2(acc[i][j][2], acc[i][j][3]);
        }
    }
}

// ------------------------------------------------------------------ launch
extern "C" void kernel_launch(void* const* d_in, const int* in_sizes, int n_in,
                              void* d_out, int out_size) {
    const float* x    = (const float*)d_in[0];
    const float* w    = (const float*)d_in[1];
    const float* mask = (const float*)d_in[2];
    float* out        = (float*)d_out;

    static bool attr_done = false;
    if (!attr_done) {
        cudaFuncSetAttribute(gemm_kernel,
                             cudaFuncAttributeMaxDynamicSharedMemorySize, SMEM_BYTES);
        attr_done = true;
    }

    build_kidx_kernel<<<1, 256>>>(mask);
    compact_x_kernel<<<(MT * KCH * 8 * 4) / 8, 256>>>(x);   // 16384 blocks
    compact_w_kernel<<<(NT * KCH * 8 * 4) / 8, 256>>>(w);   //   512 blocks
    gemm_kernel<<<dim3(NT, MT), THREADS, SMEM_BYTES>>>(out);
}

// round 5
// speedup vs baseline: 1.6140x; 1.5342x over previous
#include <cuda_runtime.h>
#include <cuda_fp16.h>
#include <cstdint>

// Geometry
#define DIN    1024
#define DOUT   1024
#define MTOT   32768            // B*S
#define K2     512              // compacted K (2:4 column-global mask)
#define BM     128
#define BN     128
#define BK     64
#define KCH    (K2 / BK)        // 8
#define MT     (MTOT / BM)      // 256
#define NT     (DOUT / BN)      // 8
#define THREADS 128
#define STAGES 3

// fp16 fragment-major compact operands.
// A tile (mt,kc) = 16KB: frag fi = mtl(8)*4 + ks(4); 512B frag, lane*16B.
//   lane 16B = {h(r,k),h(r,k+1)} {h(r+8,k),h(r+8,k+1)} {h(r,k+8),h(r,k+9)} {h(r+8,k+8),h(r+8,k+9)}
//   with r = mtl*16 + (l>>2), k = ks*16 + 2*(l&3)  (compact-k space)
// B tile (nt,kc) = 16KB: frag fj = p(8)*4 + ks(4); pair p covers ntiles 2p,2p+1.
//   lane 16B = {B[k..k+1][n0]} {B[k+8..k+9][n0]} {same n0+8}
#define A_STAGE_BYTES (BM * BK * 2)    // 16384
#define B_STAGE_BYTES (BN * BK * 2)    // 16384
__device__ __align__(128) unsigned char g_xc[(size_t)MT * KCH * A_STAGE_BYTES]; // 32 MB
__device__ __align__(128) unsigned char g_wc[(size_t)NT * KCH * B_STAGE_BYTES]; //  1 MB
__device__ int g_kidx[K2];

// ------------------------------------------------------------------ helpers
__device__ __forceinline__ uint32_t smem_u32(const void* p) {
    uint32_t a;
    asm("{ .reg .u64 t; cvta.to.shared.u64 t, %1; cvt.u32.u64 %0, t; }"
        : "=r"(a) : "l"(p));
    return a;
}
__device__ __forceinline__ uint32_t h2bits(float a, float b) {
    __half2 h = __floats2half2_rn(a, b);
    return *reinterpret_cast<uint32_t*>(&h);
}
__device__ __forceinline__ void cp16(uint32_t dst, const void* src) {
    asm volatile("cp.async.cg.shared.global [%0], [%1], 16;"
                 :: "r"(dst), "l"(src) : "memory");
}
__device__ __forceinline__ void cp_commit() {
    asm volatile("cp.async.commit_group;" ::: "memory");
}
template <int N>
__device__ __forceinline__ void cp_wait() {
    asm volatile("cp.async.wait_group %0;" :: "n"(N) : "memory");
}
__device__ __forceinline__ void lds128(uint32_t (&r)[4], uint32_t addr) {
    asm volatile("ld.shared.v4.u32 {%0,%1,%2,%3}, [%4];"
                 : "=r"(r[0]), "=r"(r[1]), "=r"(r[2]), "=r"(r[3]) : "r"(addr));
}
__device__ __forceinline__ void mma_f16(float (&d)[4], const uint32_t (&a)[4],
                                        uint32_t b0, uint32_t b1) {
    asm volatile(
        "mma.sync.aligned.m16n8k16.row.col.f32.f16.f16.f32 "
        "{%0,%1,%2,%3}, {%4,%5,%6,%7}, {%8,%9}, {%0,%1,%2,%3};"
        : "+f"(d[0]), "+f"(d[1]), "+f"(d[2]), "+f"(d[3])
        : "r"(a[0]), "r"(a[1]), "r"(a[2]), "r"(a[3]), "r"(b0), "r"(b1));
}

// ------------------------------------------------------------------ prepass
// Mask is column-global: one thread per 4-group records its 2 active columns.
__global__ void build_kidx_kernel(const float* __restrict__ mask) {
    int g = blockIdx.x * blockDim.x + threadIdx.x;   // 256 groups
    if (g >= DIN / 4) return;
    int w = 0;
    int idx[2] = {-1, -1};
    #pragma unroll
    for (int j = 0; j < 4; j++) {
        int c = g * 4 + j;
        if (mask[c] != 0.0f && w < 2) idx[w++] = c;
    }
    g_kidx[2 * g]     = idx[0];
    g_kidx[2 * g + 1] = idx[1];
}

// x compaction, smem-staged: block = (mt, kc) covers 128 rows x 128 orig cols
// (= 32 groups = 64 compact cols). Phase 1: coalesced float4 reads, select 2/4,
// convert to half2, stage in smem. Phase 2: gather into fragment order,
// coalesced 16B writes.
__global__ void __launch_bounds__(256) compact_x_kernel(const float4* __restrict__ x4) {
    __shared__ uint32_t hsw[128 * 34];   // 128 rows x 32 half2-pairs, stride 34 words
    __shared__ int s_j0[32], s_j1[32];

    const int kc = blockIdx.x & (KCH - 1);
    const int mt = blockIdx.x >> 3;
    const int tid = threadIdx.x;

    if (tid < 32) {
        int gg = kc * 32 + tid;                      // global group
        int o0 = g_kidx[2 * gg], o1 = g_kidx[2 * gg + 1];
        s_j0[tid] = (o0 >= 0) ? (o0 & 3) : -1;
        s_j1[tid] = (o1 >= 0) ? (o1 & 3) : -1;
    }
    __syncthreads();

    // phase 1: 128 rows x 32 groups = 4096 float4 reads
    #pragma unroll
    for (int i = 0; i < 16; i++) {
        int idx = tid + 256 * i;
        int row = idx >> 5, gl = idx & 31;
        float4 f = x4[(size_t)(mt * BM + row) * (DIN / 4) + kc * 32 + gl];
        int j0 = s_j0[gl], j1 = s_j1[gl];
        float v0 = (j0 == 0) ? f.x : (j0 == 1) ? f.y : (j0 == 2) ? f.z : f.w;
        float v1 = (j1 == 0) ? f.x : (j1 == 1) ? f.y : (j1 == 2) ? f.z : f.w;
        if (j0 < 0) v0 = 0.0f;
        if (j1 < 0) v1 = 0.0f;
        hsw[row * 34 + gl] = h2bits(v0, v1);
    }
    __syncthreads();

    // phase 2: 1024 uint4 fragment writes
    unsigned char* dst = g_xc + ((size_t)(mt * KCH + kc)) * A_STAGE_BYTES;
    #pragma unroll
    for (int j = 0; j < 4; j++) {
        int o = tid + 256 * j;
        int l = o & 31, fi = o >> 5;
        int ks = fi & 3, mtl = fi >> 2;
        int r = mtl * 16 + (l >> 2);
        int wb = ks * 8 + (l & 3);                   // half2-pair index in [0,32)
        uint4 v;
        v.x = hsw[r * 34 + wb];
        v.y = hsw[(r + 8) * 34 + wb];
        v.z = hsw[r * 34 + wb + 4];
        v.w = hsw[(r + 8) * 34 + wb + 4];
        *reinterpret_cast<uint4*>(dst + o * 16) = v;
    }
}

// w compaction: one warp per 512B fragment. 2048 frags -> 256 blocks x 8 warps.
__global__ void __launch_bounds__(256) compact_w_kernel(const float* __restrict__ w) {
    int fj = blockIdx.x * 8 + (threadIdx.x >> 5);
    int l  = threadIdx.x & 31;
    int ks = fj & 3;
    int p  = (fj >> 2) & 7;
    int kc = (fj >> 5) & (KCH - 1);
    int nt = fj >> 8;
    int n0 = nt * BN + p * 16 + (l >> 2);            // ntile0 col; ntile1 = n0+8
    int kk = kc * BK + ks * 16 + 2 * (l & 3);
    int k0  = g_kidx[kk],     k0b = g_kidx[kk + 1];
    int k1  = g_kidx[kk + 8], k1b = g_kidx[kk + 9];
    const float* w0 = w + (size_t)n0 * DIN;
    const float* w1 = w0 + (size_t)8 * DIN;
    float a0 = (k0  >= 0) ? __ldg(w0 + k0)  : 0.0f;
    float a1 = (k0b >= 0) ? __ldg(w0 + k0b) : 0.0f;
    float a2 = (k1  >= 0) ? __ldg(w0 + k1)  : 0.0f;
    float a3 = (k1b >= 0) ? __ldg(w0 + k1b) : 0.0f;
    float b0 = (k0  >= 0) ? __ldg(w1 + k0)  : 0.0f;
    float b1 = (k0b >= 0) ? __ldg(w1 + k0b) : 0.0f;
    float b2 = (k1  >= 0) ? __ldg(w1 + k1)  : 0.0f;
    float b3 = (k1b >= 0) ? __ldg(w1 + k1b) : 0.0f;
    uint4 v;
    v.x = h2bits(a0, a1);
    v.y = h2bits(a2, a3);
    v.z = h2bits(b0, b1);
    v.w = h2bits(b2, b3);
    *reinterpret_cast<uint4*>(g_wc + (size_t)fj * 512 + l * 16) = v;
}

// ------------------------------------------------------------------ GEMM
// smem: A stages [0, 3*16KB) then B stages [48KB, 96KB).
#define SMEM_BYTES (STAGES * (A_STAGE_BYTES + B_STAGE_BYTES))   // 98304

__global__ void __launch_bounds__(THREADS, 2) gemm_kernel(float* __restrict__ out) {
    extern __shared__ char smem[];
    const uint32_t sA0 = smem_u32(smem);
    const uint32_t sB0 = sA0 + STAGES * A_STAGE_BYTES;

    const int tid = threadIdx.x;
    const int wid = tid >> 5, lid = tid & 31;
    const int nt = blockIdx.x, mt = blockIdx.y;
    const int wm = wid & 1;         // 2 m-warps (64 rows)
    const int wn = wid >> 1;        // 2 n-warps (64 cols = 4 pairs)

    const unsigned char* gA = g_xc + ((size_t)mt * KCH) * A_STAGE_BYTES;
    const unsigned char* gB = g_wc + ((size_t)nt * KCH) * B_STAGE_BYTES;

    // stage loader: A 16KB + B 16KB, 128 threads x 16B -> 8 iters each
    auto load_stage = [&](int s, int c) {
        uint32_t dA = sA0 + s * A_STAGE_BYTES + tid * 16;
        const unsigned char* srcA = gA + (size_t)c * A_STAGE_BYTES + tid * 16;
        #pragma unroll
        for (int j = 0; j < 8; j++) cp16(dA + j * 2048, srcA + j * 2048);
        uint32_t dB = sB0 + s * B_STAGE_BYTES + tid * 16;
        const unsigned char* srcB = gB + (size_t)c * B_STAGE_BYTES + tid * 16;
        #pragma unroll
        for (int j = 0; j < 8; j++) cp16(dB + j * 2048, srcB + j * 2048);
    };

    float acc[4][8][4];
    #pragma unroll
    for (int i = 0; i < 4; i++)
        #pragma unroll
        for (int j = 0; j < 8; j++)
            #pragma unroll
            for (int v = 0; v < 4; v++) acc[i][j][v] = 0.0f;

    uint32_t ab[2][4][4], bb[2][4][4];
    auto ldfrags = [&](int buf, int s, int ks) {
        const uint32_t aB = sA0 + s * A_STAGE_BYTES + ((wm * 4) * 4 + ks) * 512 + lid * 16;
        #pragma unroll
        for (int i = 0; i < 4; i++) lds128(ab[buf][i], aB + i * 2048);
        const uint32_t bB = sB0 + s * B_STAGE_BYTES + ((wn * 4) * 4 + ks) * 512 + lid * 16;
        #pragma unroll
        for (int p = 0; p < 4; p++) lds128(bb[buf][p], bB + p * 2048);
    };
    auto domma = [&](int buf) {
        #pragma unroll
        for (int i = 0; i < 4; i++)
            #pragma unroll
            for (int p = 0; p < 4; p++) {
                mma_f16(acc[i][2 * p],     ab[buf][i], bb[buf][p][0], bb[buf][p][1]);
                mma_f16(acc[i][2 * p + 1], ab[buf][i], bb[buf][p][2], bb[buf][p][3]);
            }
    };

    // prologue: fill stages 0,1; load ks0 frags of chunk 0
    load_stage(0, 0); cp_commit();
    load_stage(1, 1); cp_commit();
    cp_wait<1>();
    __syncthreads();
    ldfrags(0, 0, 0);

    int s = 0;
    for (int c = 0; c < KCH; c++) {
        const int snext = (s == STAGES - 1) ? 0 : s + 1;
        const int sload = (snext == STAGES - 1) ? 0 : snext + 1;
        if (c + 2 < KCH) load_stage(sload, c + 2);
        cp_commit();

        ldfrags(1, s, 1); domma(0);     // ks0 compute, ks1 prefetch
        ldfrags(0, s, 2); domma(1);     // ks1
        ldfrags(1, s, 3); domma(0);     // ks2
        cp_wait<1>();                   // chunk c+1 resident (c+2 may pend)
        __syncthreads();                // visible to all; stage s fully read
        if (c + 1 < KCH) ldfrags(0, snext, 0);
        domma(1);                       // ks3
        s = snext;
    }

    // epilogue: d frag (r,2c): d0,d1 @ row r; d2,d3 @ row r+8
    const int rowW = mt * BM + wm * 64 + (lid >> 2);
    const int colW = nt * BN + wn * 64 + (lid & 3) * 2;
    #pragma unroll
    for (int i = 0; i < 4; i++) {
        const size_t r0 = (size_t)(rowW + i * 16) * DOUT;
        const size_t r1 = r0 + (size_t)8 * DOUT;
        #pragma unroll
        for (int j = 0; j < 8; j++) {
            const int cc = colW + j * 8;
            *reinterpret_cast<float2*>(out + r0 + cc) =
                make_float2(acc[i][j][0], acc[i][j][1]);
            *reinterpret_cast<float2*>(out + r1 + cc) =
                make_float2(acc[i][j][2], acc[i][j][3]);
        }
    }
}

// ------------------------------------------------------------------ launch
extern "C" void kernel_launch(void* const* d_in, const int* in_sizes, int n_in,
                              void* d_out, int out_size) {
    const float* x    = (const float*)d_in[0];
    const float* w    = (const float*)d_in[1];
    const float* mask = (const float*)d_in[2];
    float* out        = (float*)d_out;

    cudaFuncSetAttribute(gemm_kernel,
                         cudaFuncAttributeMaxDynamicSharedMemorySize, SMEM_BYTES);

    build_kidx_kernel<<<1, 256>>>(mask);
    compact_x_kernel<<<MT * KCH, 256>>>((const float4*)x);   // 2048 blocks
    compact_w_kernel<<<(NT * KCH * 8 * 4) / 8, 256>>>(w);    //  256 blocks
    gemm_kernel<<<dim3(NT, MT), THREADS, SMEM_BYTES>>>(out);
}